// round 2
// baseline (speedup 1.0000x reference)
#include <cuda_runtime.h>
#include <math.h>

#define BDIM 8192
#define DDIM 256

// ---------------- device scratch (allocation-free workaround) ----------------
__device__ float    g_sim[(size_t)BDIM * BDIM];   // 256 MB sim matrix
__device__ unsigned g_minpos[BDIM];               // ordered-uint encoded float
__device__ unsigned g_maxneg[BDIM];
__device__ int      g_lab[BDIM];
__device__ float    g_rowloss[BDIM];
__device__ float    g_validf[BDIM];

// monotone float<->uint order mapping (handles negatives)
__device__ __forceinline__ unsigned ordf(float f) {
    unsigned u = __float_as_uint(f);
    return (u & 0x80000000u) ? ~u : (u | 0x80000000u);
}
__device__ __forceinline__ float unordf(unsigned u) {
    unsigned b = (u & 0x80000000u) ? (u ^ 0x80000000u) : ~u;
    return __uint_as_float(b);
}

#define ORD_PINF 0xFF800000u  /* ordf(+inf) */
#define ORD_NINF 0x007FFFFFu  /* ordf(-inf) */

// ---------------- kernel 0: label load with dtype sniffing + init ----------
// The reference asks for jnp.int64 labels, but default JAX canonicalizes to
// int32. Detect at runtime: if the buffer is int64 (LE, values < 512), every
// odd 32-bit word is 0. If int32, odd words are random labels (all-zero has
// probability 512^-4096). The scan reads exactly 8192 int32 words — in
// bounds for both layouts.
__global__ void k_load_labels(const int* __restrict__ labels_raw) {
    __shared__ int s_nonzero_odd;
    const int t = threadIdx.x;
    if (t == 0) s_nonzero_odd = 0;
    __syncthreads();

    int local_or = 0;
    for (int i = t; i < BDIM / 2; i += blockDim.x)
        local_or |= labels_raw[2 * i + 1];
    if (local_or) atomicOr(&s_nonzero_odd, 1);
    __syncthreads();

    const bool is64 = (s_nonzero_odd == 0);
    for (int i = t; i < BDIM; i += blockDim.x) {
        g_lab[i]    = is64 ? labels_raw[2 * i] : labels_raw[i];
        g_minpos[i] = ORD_PINF;
        g_maxneg[i] = ORD_NINF;
    }
}

// ---------------- kernel 1: SGEMM (A * A^T) + fused row min/max epilogue ----
#define BM 128
#define BN 128
#define BK 16
#define TM 8
#define TN 8

__global__ __launch_bounds__(256, 2)
void k_gemm_minmax(const float* __restrict__ A) {
    __shared__ float As[BK][BM + 4];
    __shared__ float Bs[BK][BN + 4];

    const int t    = threadIdx.x;
    const int trow = t >> 4;   // 0..15
    const int tcol = t & 15;   // 0..15
    const int rowBase = blockIdx.y * BM;
    const int colBase = blockIdx.x * BN;

    float acc[TM][TN];
#pragma unroll
    for (int i = 0; i < TM; i++)
#pragma unroll
        for (int j = 0; j < TN; j++) acc[i][j] = 0.0f;

    for (int k0 = 0; k0 < DDIM; k0 += BK) {
#pragma unroll
        for (int i = 0; i < 2; i++) {
            int l  = t + i * 256;          // 0..511
            int lr = l >> 2;               // 0..127 tile row
            int lk = (l & 3) * 4;          // 0,4,8,12
            float4 va = *(const float4*)&A[(size_t)(rowBase + lr) * DDIM + k0 + lk];
            As[lk + 0][lr] = va.x; As[lk + 1][lr] = va.y;
            As[lk + 2][lr] = va.z; As[lk + 3][lr] = va.w;
            float4 vb = *(const float4*)&A[(size_t)(colBase + lr) * DDIM + k0 + lk];
            Bs[lk + 0][lr] = vb.x; Bs[lk + 1][lr] = vb.y;
            Bs[lk + 2][lr] = vb.z; Bs[lk + 3][lr] = vb.w;
        }
        __syncthreads();

#pragma unroll
        for (int kk = 0; kk < BK; kk++) {
            float ra[TM], rb[TN];
#pragma unroll
            for (int i = 0; i < TM; i++) ra[i] = As[kk][trow * TM + i];
#pragma unroll
            for (int j = 0; j < TN; j++) rb[j] = Bs[kk][tcol * TN + j];
#pragma unroll
            for (int i = 0; i < TM; i++)
#pragma unroll
                for (int j = 0; j < TN; j++) acc[i][j] += ra[i] * rb[j];
        }
        __syncthreads();
    }

    // epilogue: store sim tile + per-row min(pos)/max(neg)
    const float POSLIM = 1.0f - 1e-5f;
    int lj[TN];
#pragma unroll
    for (int j = 0; j < TN; j++) lj[j] = g_lab[colBase + tcol * TN + j];

#pragma unroll
    for (int i = 0; i < TM; i++) {
        int row = rowBase + trow * TM + i;
        int li  = g_lab[row];

        float4 s0 = make_float4(acc[i][0], acc[i][1], acc[i][2], acc[i][3]);
        float4 s1 = make_float4(acc[i][4], acc[i][5], acc[i][6], acc[i][7]);
        size_t base = (size_t)row * BDIM + colBase + tcol * TN;
        *(float4*)&g_sim[base]     = s0;
        *(float4*)&g_sim[base + 4] = s1;

        float mn = __uint_as_float(0x7f800000u);   // +inf
        float mx = __uint_as_float(0xff800000u);   // -inf
#pragma unroll
        for (int j = 0; j < TN; j++) {
            float s = acc[i][j];
            if (li == lj[j]) {
                if (s < POSLIM) mn = fminf(mn, s);
            } else {
                mx = fmaxf(mx, s);
            }
        }
        // reduce across the 16 tcol lanes (xor offsets 1..8 stay in-half)
#pragma unroll
        for (int o = 1; o < 16; o <<= 1) {
            mn = fminf(mn, __shfl_xor_sync(0xffffffffu, mn, o));
            mx = fmaxf(mx, __shfl_xor_sync(0xffffffffu, mx, o));
        }
        if (tcol == 0) {
            atomicMin(&g_minpos[row], ordf(mn));
            atomicMax(&g_maxneg[row], ordf(mx));
        }
    }
}

// ---------------- kernel 2: per-row masked exp-sums ----------------
__global__ __launch_bounds__(256)
void k_rowpass() {
    const int i = blockIdx.x;
    const int t = threadIdx.x;
    const int li = g_lab[i];

    const float minpos = unordf(g_minpos[i]);
    const float maxneg = unordf(g_maxneg[i]);
    const float tn = minpos - 0.1f;   // neg_sel: sim >  tn
    const float tp = maxneg + 0.1f;   // pos_sel: sim <  tp
    const float POSLIM = 1.0f - 1e-5f;

    float psum = 0.0f, nsum = 0.0f;
    int   pany = 0,    nany = 0;

    const float4* simrow = (const float4*)&g_sim[(size_t)i * BDIM];
    const int4*   lab4   = (const int4*)g_lab;

    for (int j4 = t; j4 < BDIM / 4; j4 += 256) {
        float4 v = simrow[j4];
        int4   L = lab4[j4];
        float sv[4] = {v.x, v.y, v.z, v.w};
        int   lv[4] = {L.x, L.y, L.z, L.w};
#pragma unroll
        for (int c = 0; c < 4; c++) {
            float s = sv[c];
            if (lv[c] == li) {
                if (s < POSLIM && s < tp) {
                    pany = 1;
                    psum += expf(-2.0f * (s - 0.5f));
                }
            } else {
                if (s > tn) {
                    nany = 1;
                    // exp(50*(s-0.5)) < 2e-9 for s < 0.1 -> negligible vs log1p/50
                    if (s >= 0.1f) nsum += expf(50.0f * (s - 0.5f));
                }
            }
        }
    }

    __shared__ float sp[256], sn[256];
    __shared__ int   fp[256], fn[256];
    sp[t] = psum; sn[t] = nsum; fp[t] = pany; fn[t] = nany;
    __syncthreads();
    for (int o = 128; o > 0; o >>= 1) {
        if (t < o) {
            sp[t] += sp[t + o];
            sn[t] += sn[t + o];
            fp[t] |= fp[t + o];
            fn[t] |= fn[t + o];
        }
        __syncthreads();
    }
    if (t == 0) {
        bool valid = fp[0] && fn[0];
        float row_loss = 0.5f * log1pf(sp[0]) + 0.02f * log1pf(sn[0]);
        g_rowloss[i] = valid ? row_loss : 0.0f;
        g_validf[i]  = valid ? 1.0f : 0.0f;
    }
}

// ---------------- kernel 3: deterministic final reduction ----------------
__global__ void k_final(float* __restrict__ out, int out_size) {
    __shared__ float sl[256], sv[256];
    int t = threadIdx.x;
    float ls = 0.0f, vs = 0.0f;
    for (int i = t; i < BDIM; i += 256) {
        ls += g_rowloss[i];
        vs += g_validf[i];
    }
    sl[t] = ls; sv[t] = vs;
    __syncthreads();
    for (int o = 128; o > 0; o >>= 1) {
        if (t < o) { sl[t] += sl[t + o]; sv[t] += sv[t + o]; }
        __syncthreads();
    }
    if (t == 0) {
        if (out_size > 0) out[0] = sl[0] / (float)BDIM;           // loss
        if (out_size > 1) out[1] = 1.0f - sv[0] / (float)BDIM;    // prec1
    }
}

// ---------------- launch ----------------
extern "C" void kernel_launch(void* const* d_in, const int* in_sizes, int n_in,
                              void* d_out, int out_size) {
    const float* feats  = (const float*)d_in[0];   // [8192, 256] f32
    const int*   labels = (const int*)d_in[1];     // [8192] int32 OR int64 (sniffed)
    float* out = (float*)d_out;

    k_load_labels<<<1, 1024>>>(labels);

    dim3 grid(BDIM / BN, BDIM / BM);
    k_gemm_minmax<<<grid, 256>>>(feats);

    k_rowpass<<<BDIM, 256>>>();

    k_final<<<1, 256>>>(out, out_size);
}

// round 3
// speedup vs baseline: 1.5712x; 1.5712x over previous
#include <cuda_runtime.h>
#include <math.h>

#define BDIM 8192
#define DDIM 256
#define NBLK (BDIM / 128)          /* 64 block-rows */
#define NTILES (NBLK * (NBLK + 1) / 2)  /* 2080 upper-triangular tiles */

// ---------------- device scratch (allocation-free workaround) ----------------
__device__ float    g_sim[(size_t)BDIM * BDIM];   // 256 MB sim matrix
__device__ unsigned g_minpos[BDIM];               // ordered-uint encoded float
__device__ unsigned g_maxneg[BDIM];
__device__ int      g_lab[BDIM];
__device__ float    g_rowloss[BDIM];
__device__ float    g_validf[BDIM];

// monotone float<->uint order mapping (handles negatives)
__device__ __forceinline__ unsigned ordf(float f) {
    unsigned u = __float_as_uint(f);
    return (u & 0x80000000u) ? ~u : (u | 0x80000000u);
}
__device__ __forceinline__ float unordf(unsigned u) {
    unsigned b = (u & 0x80000000u) ? (u ^ 0x80000000u) : ~u;
    return __uint_as_float(b);
}

#define ORD_PINF 0xFF800000u  /* ordf(+inf) */
#define ORD_NINF 0x007FFFFFu  /* ordf(-inf) */

// ---------------- kernel 0: label load with dtype sniffing + init ----------
// Reference requests jnp.int64 labels but default JAX canonicalizes to int32.
// If int64 (LE, values < 512) every odd 32-bit word is 0; if int32 odd words
// are random labels. Scan reads exactly 8192 int32 words — in bounds either way.
__global__ void k_load_labels(const int* __restrict__ labels_raw) {
    __shared__ int s_nonzero_odd;
    const int t = threadIdx.x;
    if (t == 0) s_nonzero_odd = 0;
    __syncthreads();

    int local_or = 0;
    for (int i = t; i < BDIM / 2; i += blockDim.x)
        local_or |= labels_raw[2 * i + 1];
    if (local_or) atomicOr(&s_nonzero_odd, 1);
    __syncthreads();

    const bool is64 = (s_nonzero_odd == 0);
    for (int i = t; i < BDIM; i += blockDim.x) {
        g_lab[i]    = is64 ? labels_raw[2 * i] : labels_raw[i];
        g_minpos[i] = ORD_PINF;
        g_maxneg[i] = ORD_NINF;
    }
}

// ---------------- kernel 1: symmetric SGEMM (A * A^T) -----------------------
// Only upper-triangular 128x128 block tiles are computed. Each off-diagonal
// tile is stored twice (direct + smem-staged transpose) and contributes row
// stats (rows of block bi) AND column stats (rows of block bj).
#define BM 128
#define BN 128
#define BK 16
#define TM 8
#define TN 8

__global__ __launch_bounds__(256, 2)
void k_gemm_minmax(const float* __restrict__ A) {
    // As/Bs for mainloop; same storage reused as 32x128 transpose buffer after.
    __shared__ float smem_raw[2 * BK * (BM + 4)];     // 4224 floats = 16896 B
    float (*As)[BM + 4] = (float (*)[BM + 4])smem_raw;
    float (*Bs)[BN + 4] = (float (*)[BN + 4])(smem_raw + BK * (BM + 4));
    float (*tbuf)[128]  = (float (*)[128])smem_raw;   // 32x128 = 16384 floats

    __shared__ unsigned s_cmin[128], s_cmax[128];     // ordered-uint col stats

    const int t    = threadIdx.x;
    const int trow = t >> 4;   // 0..15
    const int tcol = t & 15;   // 0..15

    // decode upper-triangular tile index: L -> (bi, bj), bj >= bi
    int L = blockIdx.x;
    int bi = (int)((129.0 - sqrt((double)(129 * 129 - 8 * L))) * 0.5);
    while (bi * (129 - bi) / 2 > L) bi--;
    while ((bi + 1) * (129 - (bi + 1)) / 2 <= L) bi++;
    const int bj = bi + (L - bi * (129 - bi) / 2);
    const int rowBase = bi * BM;
    const int colBase = bj * BN;
    const bool offdiag = (bi != bj);

    // init shared column stats (synced by the first mainloop __syncthreads)
    if (t < 128) { s_cmin[t] = ORD_PINF; s_cmax[t] = ORD_NINF; }

    float acc[TM][TN];
#pragma unroll
    for (int i = 0; i < TM; i++)
#pragma unroll
        for (int j = 0; j < TN; j++) acc[i][j] = 0.0f;

    for (int k0 = 0; k0 < DDIM; k0 += BK) {
#pragma unroll
        for (int i = 0; i < 2; i++) {
            int l  = t + i * 256;          // 0..511
            int lr = l >> 2;               // 0..127 tile row
            int lk = (l & 3) * 4;          // 0,4,8,12
            float4 va = *(const float4*)&A[(size_t)(rowBase + lr) * DDIM + k0 + lk];
            As[lk + 0][lr] = va.x; As[lk + 1][lr] = va.y;
            As[lk + 2][lr] = va.z; As[lk + 3][lr] = va.w;
            float4 vb = *(const float4*)&A[(size_t)(colBase + lr) * DDIM + k0 + lk];
            Bs[lk + 0][lr] = vb.x; Bs[lk + 1][lr] = vb.y;
            Bs[lk + 2][lr] = vb.z; Bs[lk + 3][lr] = vb.w;
        }
        __syncthreads();

#pragma unroll
        for (int kk = 0; kk < BK; kk++) {
            float ra[TM], rb[TN];
#pragma unroll
            for (int i = 0; i < TM; i++) ra[i] = As[kk][trow * TM + i];
#pragma unroll
            for (int j = 0; j < TN; j++) rb[j] = Bs[kk][tcol * TN + j];
#pragma unroll
            for (int i = 0; i < TM; i++)
#pragma unroll
                for (int j = 0; j < TN; j++) acc[i][j] += ra[i] * rb[j];
        }
        __syncthreads();
    }

    const float POSLIM = 1.0f - 1e-5f;
    const float PINF = __uint_as_float(0x7f800000u);
    const float NINF = __uint_as_float(0xff800000u);

    int lj[TN], lrow[TM];
#pragma unroll
    for (int j = 0; j < TN; j++) lj[j] = g_lab[colBase + tcol * TN + j];
#pragma unroll
    for (int i = 0; i < TM; i++) lrow[i] = g_lab[rowBase + trow * TM + i];

    // ---- row stats (rows of block bi over cols of block bj) + direct store
#pragma unroll
    for (int i = 0; i < TM; i++) {
        const int row = rowBase + trow * TM + i;
        const int li  = lrow[i];

        float4 s0 = make_float4(acc[i][0], acc[i][1], acc[i][2], acc[i][3]);
        float4 s1 = make_float4(acc[i][4], acc[i][5], acc[i][6], acc[i][7]);
        size_t base = (size_t)row * BDIM + colBase + tcol * TN;
        *(float4*)&g_sim[base]     = s0;
        *(float4*)&g_sim[base + 4] = s1;

        float mn = PINF, mx = NINF;
#pragma unroll
        for (int j = 0; j < TN; j++) {
            float s = acc[i][j];
            if (li == lj[j]) {
                if (s < POSLIM) mn = fminf(mn, s);
            } else {
                mx = fmaxf(mx, s);
            }
        }
#pragma unroll
        for (int o = 1; o < 16; o <<= 1) {
            mn = fminf(mn, __shfl_xor_sync(0xffffffffu, mn, o));
            mx = fmaxf(mx, __shfl_xor_sync(0xffffffffu, mx, o));
        }
        if (tcol == 0) {
            atomicMin(&g_minpos[row], ordf(mn));
            atomicMax(&g_maxneg[row], ordf(mx));
        }
    }

    if (offdiag) {
        // ---- column stats (rows of block bj over cols of block bi)
#pragma unroll
        for (int j = 0; j < TN; j++) {
            float cmn = PINF, cmx = NINF;
#pragma unroll
            for (int i = 0; i < TM; i++) {
                float s = acc[i][j];
                if (lrow[i] == lj[j]) {
                    if (s < POSLIM) cmn = fminf(cmn, s);
                } else {
                    cmx = fmaxf(cmx, s);
                }
            }
            atomicMin(&s_cmin[tcol * TN + j], ordf(cmn));
            atomicMax(&s_cmax[tcol * TN + j], ordf(cmx));
        }
        __syncthreads();
        if (t < 128) {
            if (s_cmin[t] != ORD_PINF) atomicMin(&g_minpos[colBase + t], s_cmin[t]);
            if (s_cmax[t] != ORD_NINF) atomicMax(&g_maxneg[colBase + t], s_cmax[t]);
        }

        // ---- transposed store via smem staging (coalesced 128B rows)
        // chunk q covers tile columns [q*32, q*32+32), handled by tcol in [q*4,(q+1)*4)
#pragma unroll
        for (int q = 0; q < 4; q++) {
            __syncthreads();   // previous chunk's reads done / mainloop done
            if ((tcol >> 2) == q) {
                const int cbase = (tcol & 3) * TN;   // column slot in chunk
#pragma unroll
                for (int j = 0; j < TN; j++)
#pragma unroll
                    for (int i = 0; i < TM; i++)
                        tbuf[cbase + j][trow * TM + i] = acc[i][j];
            }
            __syncthreads();
            // 1024 float4 stores: warp = one 128-float row
#pragma unroll
            for (int k = 0; k < 4; k++) {
                int f4  = t + k * 256;
                int cl  = f4 >> 5;         // 0..31 column-local
                int pos = (f4 & 31) * 4;   // float offset in row
                float4 v = *(const float4*)&tbuf[cl][pos];
                *(float4*)&g_sim[(size_t)(colBase + q * 32 + cl) * BDIM + rowBase + pos] = v;
            }
        }
    }
}

// ---------------- kernel 2: per-row masked exp-sums ----------------
__global__ __launch_bounds__(256)
void k_rowpass() {
    const int i = blockIdx.x;
    const int t = threadIdx.x;
    const int li = g_lab[i];

    const float minpos = unordf(g_minpos[i]);
    const float maxneg = unordf(g_maxneg[i]);
    const float tn = minpos - 0.1f;   // neg_sel: sim >  tn
    const float tp = maxneg + 0.1f;   // pos_sel: sim <  tp
    const float POSLIM = 1.0f - 1e-5f;

    float psum = 0.0f, nsum = 0.0f;
    int   pany = 0,    nany = 0;

    const float4* simrow = (const float4*)&g_sim[(size_t)i * BDIM];
    const int4*   lab4   = (const int4*)g_lab;

    for (int j4 = t; j4 < BDIM / 4; j4 += 256) {
        float4 v = simrow[j4];
        int4   L = lab4[j4];
        float sv[4] = {v.x, v.y, v.z, v.w};
        int   lv[4] = {L.x, L.y, L.z, L.w};
#pragma unroll
        for (int c = 0; c < 4; c++) {
            float s = sv[c];
            if (lv[c] == li) {
                if (s < POSLIM && s < tp) {
                    pany = 1;
                    psum += expf(-2.0f * (s - 0.5f));
                }
            } else {
                if (s > tn) {
                    nany = 1;
                    // exp(50*(s-0.5)) < 2e-9 for s < 0.1 -> negligible vs log1p/50
                    if (s >= 0.1f) nsum += expf(50.0f * (s - 0.5f));
                }
            }
        }
    }

    __shared__ float sp[256], sn[256];
    __shared__ int   fp[256], fn[256];
    sp[t] = psum; sn[t] = nsum; fp[t] = pany; fn[t] = nany;
    __syncthreads();
    for (int o = 128; o > 0; o >>= 1) {
        if (t < o) {
            sp[t] += sp[t + o];
            sn[t] += sn[t + o];
            fp[t] |= fp[t + o];
            fn[t] |= fn[t + o];
        }
        __syncthreads();
    }
    if (t == 0) {
        bool valid = fp[0] && fn[0];
        float row_loss = 0.5f * log1pf(sp[0]) + 0.02f * log1pf(sn[0]);
        g_rowloss[i] = valid ? row_loss : 0.0f;
        g_validf[i]  = valid ? 1.0f : 0.0f;
    }
}

// ---------------- kernel 3: deterministic final reduction ----------------
__global__ void k_final(float* __restrict__ out, int out_size) {
    __shared__ float sl[256], sv[256];
    int t = threadIdx.x;
    float ls = 0.0f, vs = 0.0f;
    for (int i = t; i < BDIM; i += 256) {
        ls += g_rowloss[i];
        vs += g_validf[i];
    }
    sl[t] = ls; sv[t] = vs;
    __syncthreads();
    for (int o = 128; o > 0; o >>= 1) {
        if (t < o) { sl[t] += sl[t + o]; sv[t] += sv[t + o]; }
        __syncthreads();
    }
    if (t == 0) {
        if (out_size > 0) out[0] = sl[0] / (float)BDIM;           // loss
        if (out_size > 1) out[1] = 1.0f - sv[0] / (float)BDIM;    // prec1
    }
}

// ---------------- launch ----------------
extern "C" void kernel_launch(void* const* d_in, const int* in_sizes, int n_in,
                              void* d_out, int out_size) {
    const float* feats  = (const float*)d_in[0];   // [8192, 256] f32
    const int*   labels = (const int*)d_in[1];     // [8192] int32 OR int64 (sniffed)
    float* out = (float*)d_out;

    k_load_labels<<<1, 1024>>>(labels);

    k_gemm_minmax<<<NTILES, 256>>>(feats);

    k_rowpass<<<BDIM, 256>>>();

    k_final<<<1, 256>>>(out, out_size);
}

// round 5
// speedup vs baseline: 2.2047x; 1.4033x over previous
#include <cuda_runtime.h>
#include <cuda_bf16.h>
#include <math.h>
#include <stdint.h>

#define BDIM 8192
#define DDIM 256
#define NBLK (BDIM / 128)
#define NTILES (NBLK * (NBLK + 1) / 2)   /* 2080 upper-triangular tiles */

// ---------------- device scratch (allocation-free workaround) ----------------
__device__ float         g_sim[(size_t)BDIM * BDIM];   // 256 MB
__device__ __nv_bfloat16 g_hi[BDIM * DDIM];            // bf16 high part
__device__ __nv_bfloat16 g_lo[BDIM * DDIM];            // bf16 residual
__device__ int           g_lab[BDIM];
__device__ float         g_rowloss[BDIM];
__device__ float         g_validf[BDIM];

// ---------------- portable PTX helpers (sm_80+, pass plain sm_103 target) ---
__device__ __forceinline__ uint32_t smem_u32(const void* p) {
    uint32_t a;
    asm("{ .reg .u64 t; cvta.to.shared.u64 t, %1; cvt.u32.u64 %0, t; }" : "=r"(a) : "l"(p));
    return a;
}
#define CP_ASYNC16(dst, src) \
    asm volatile("cp.async.cg.shared.global [%0], [%1], 16;" :: "r"(dst), "l"(src) : "memory")
#define CP_COMMIT()  asm volatile("cp.async.commit_group;" ::: "memory")
#define CP_WAIT(n)   asm volatile("cp.async.wait_group %0;" :: "n"(n) : "memory")

__device__ __forceinline__ void ldm_x4(uint32_t* r, uint32_t addr) {
    asm volatile("ldmatrix.sync.aligned.m8n8.x4.shared.b16 {%0,%1,%2,%3}, [%4];"
                 : "=r"(r[0]), "=r"(r[1]), "=r"(r[2]), "=r"(r[3]) : "r"(addr));
}
__device__ __forceinline__ void mma_bf16(float* d, const uint32_t* a, const uint32_t* b) {
    asm volatile("mma.sync.aligned.m16n8k16.row.col.f32.bf16.bf16.f32 "
                 "{%0,%1,%2,%3}, {%4,%5,%6,%7}, {%8,%9}, {%0,%1,%2,%3};"
                 : "+f"(d[0]), "+f"(d[1]), "+f"(d[2]), "+f"(d[3])
                 : "r"(a[0]), "r"(a[1]), "r"(a[2]), "r"(a[3]), "r"(b[0]), "r"(b[1]));
}

// ---------------- kernel 0: labels (dtype-sniffing) ----------------
__global__ void k_load_labels(const int* __restrict__ labels_raw) {
    __shared__ int s_nonzero_odd;
    const int t = threadIdx.x;
    if (t == 0) s_nonzero_odd = 0;
    __syncthreads();
    int local_or = 0;
    for (int i = t; i < BDIM / 2; i += blockDim.x)
        local_or |= labels_raw[2 * i + 1];
    if (local_or) atomicOr(&s_nonzero_odd, 1);
    __syncthreads();
    const bool is64 = (s_nonzero_odd == 0);
    for (int i = t; i < BDIM; i += blockDim.x)
        g_lab[i] = is64 ? labels_raw[2 * i] : labels_raw[i];
}

// ---------------- kernel 1: bf16 split ----------------
__global__ void k_split(const float* __restrict__ feats) {
    int i = blockIdx.x * blockDim.x + threadIdx.x;
    if (i < BDIM * DDIM) {
        float a = feats[i];
        __nv_bfloat16 h = __float2bfloat16(a);
        g_hi[i] = h;
        g_lo[i] = __float2bfloat16(a - __bfloat162float(h));
    }
}

// ---------------- kernel 2: symmetric bf16 mma.sync GEMM --------------------
// 128x128 CTA tile, 8 warps (4 row x 2 col), warp tile 32x64.
// 12 K-chunks: 3 products (hi*hi, hi*lo, lo*hi) x 4 chunks of K=64.
// SMEM: padded pitch 144B (72 bf16) -> conflict-free ldmatrix; 3-stage cp.async.
#define PITCH   72
#define CHUNKB  (128 * 144)           /* 18432 B per (tile,side) chunk */
#define NSTAGE  3
#define GEMM_SMEM (NSTAGE * 2 * CHUNKB)   /* 110592 B */

__global__ __launch_bounds__(256, 2)
void k_gemm() {
    extern __shared__ char dsm[];
    const uint32_t sbase = smem_u32(dsm);

    const int t    = threadIdx.x;
    const int lane = t & 31;
    const int wid  = t >> 5;
    const int wrow = wid & 3;          // 0..3
    const int wcol = wid >> 2;         // 0..1

    // decode upper-triangular tile index
    int L = blockIdx.x;
    int bi = (int)((129.0 - sqrt((double)(129 * 129 - 8 * L))) * 0.5);
    while (bi * (129 - bi) / 2 > L) bi--;
    while ((bi + 1) * (129 - (bi + 1)) / 2 <= L) bi++;
    const int bj = bi + (L - bi * (129 - bi) / 2);
    const int rowBase = bi * 128;
    const int colBase = bj * 128;
    const bool offdiag = (bi != bj);

    float acc[2][8][4];
#pragma unroll
    for (int mt = 0; mt < 2; mt++)
#pragma unroll
        for (int nt = 0; nt < 8; nt++)
#pragma unroll
            for (int e = 0; e < 4; e++) acc[mt][nt][e] = 0.0f;

    // chunk loader: idx -> product p = idx>>2, k-chunk kc = idx&3
    auto load_chunk = [&](int idx, int stage) {
        const int p  = idx >> 2;
        const int kc = idx & 3;
        const __nv_bfloat16* rs = (p == 2) ? g_lo : g_hi;
        const __nv_bfloat16* cs = (p == 1) ? g_lo : g_hi;
        const uint32_t rdst = sbase + (stage * 2 + 0) * CHUNKB;
        const uint32_t cdst = sbase + (stage * 2 + 1) * CHUNKB;
        const char* rsrc = (const char*)rs + (size_t)rowBase * 512 + kc * 128;
        const char* csrc = (const char*)cs + (size_t)colBase * 512 + kc * 128;
#pragma unroll
        for (int i = 0; i < 4; i++) {
            int id = t + i * 256;            // 0..1023
            int r  = id >> 3;                // row 0..127
            int c  = (id & 7) * 16;          // byte col 0..112
            CP_ASYNC16(rdst + r * 144 + c, rsrc + (size_t)r * 512 + c);
            CP_ASYNC16(cdst + r * 144 + c, csrc + (size_t)r * 512 + c);
        }
    };

    load_chunk(0, 0); CP_COMMIT();
    load_chunk(1, 1); CP_COMMIT();

    const int lr = lane & 15;
    const int lc = (lane >> 4) * 16;

    for (int idx = 0; idx < 12; idx++) {
        if (idx + 2 < 12) {
            load_chunk(idx + 2, (idx + 2) % 3);
            CP_COMMIT();
            CP_WAIT(2);
        } else {
            CP_WAIT(0);
        }
        __syncthreads();

        const int stage = idx % 3;
        const uint32_t rb = sbase + (stage * 2 + 0) * CHUNKB;
        const uint32_t cb = sbase + (stage * 2 + 1) * CHUNKB;

#pragma unroll
        for (int kk = 0; kk < 4; kk++) {
            uint32_t a[2][4];
#pragma unroll
            for (int mt = 0; mt < 2; mt++)
                ldm_x4(a[mt], rb + (wrow * 32 + mt * 16 + lr) * 144 + kk * 32 + lc);
            uint32_t b[8][2];
#pragma unroll
            for (int n2 = 0; n2 < 4; n2++) {
                uint32_t q[4];
                ldm_x4(q, cb + (wcol * 64 + n2 * 16 + lr) * 144 + kk * 32 + lc);
                b[n2 * 2 + 0][0] = q[0]; b[n2 * 2 + 0][1] = q[2];
                b[n2 * 2 + 1][0] = q[1]; b[n2 * 2 + 1][1] = q[3];
            }
#pragma unroll
            for (int mt = 0; mt < 2; mt++)
#pragma unroll
                for (int nt = 0; nt < 8; nt++)
                    mma_bf16(acc[mt][nt], a[mt], b[nt]);
        }
        __syncthreads();
    }

    // ---- epilogue: direct store + transposed mirror (both coalesced enough)
    const int rq = lane >> 2;            // 0..7 row within 8-row group
    const int cq = (lane & 3) * 2;       // 0,2,4,6 col pair
#pragma unroll
    for (int mt = 0; mt < 2; mt++) {
#pragma unroll
        for (int h = 0; h < 2; h++) {
            const int row = rowBase + wrow * 32 + mt * 16 + h * 8 + rq;
            float* dst = &g_sim[(size_t)row * BDIM + colBase + wcol * 64 + cq];
#pragma unroll
            for (int nt = 0; nt < 8; nt++) {
                float2 v = make_float2(acc[mt][nt][h * 2 + 0], acc[mt][nt][h * 2 + 1]);
                *(float2*)(dst + nt * 8) = v;
            }
        }
    }
    if (offdiag) {
#pragma unroll
        for (int nt = 0; nt < 8; nt++) {
            const int col0 = colBase + wcol * 64 + nt * 8 + cq;
#pragma unroll
            for (int e = 0; e < 2; e++) {
                float* dst = &g_sim[(size_t)(col0 + e) * BDIM + rowBase + wrow * 32];
#pragma unroll
                for (int mt = 0; mt < 2; mt++) {
#pragma unroll
                    for (int h = 0; h < 2; h++)
                        dst[mt * 16 + h * 8 + rq] = acc[mt][nt][h * 2 + e];
                }
            }
        }
    }
}

// ---------------- kernel 3: fused stats + masked exp-sums (row in SMEM) -----
#define ROW_SMEM (BDIM * 4 + BDIM * 4)   /* srow f32 + slab i32 = 64 KB */

__global__ __launch_bounds__(256)
void k_row() {
    extern __shared__ char rsm[];
    float* srow = (float*)rsm;
    int*   slab = (int*)(rsm + BDIM * 4);

    const int i = blockIdx.x;
    const int t = threadIdx.x;
    const int li = g_lab[i];
    const float POSLIM = 1.0f - 1e-5f;

    // pass 1: stage row + labels, compute min(pos)/max(neg)
    float mn = __uint_as_float(0x7f800000u);
    float mx = __uint_as_float(0xff800000u);
    const float4* simrow = (const float4*)&g_sim[(size_t)i * BDIM];
    const int4*   lab4   = (const int4*)g_lab;
    for (int j4 = t; j4 < BDIM / 4; j4 += 256) {
        float4 v  = simrow[j4];
        int4   Lv = lab4[j4];
        ((float4*)srow)[j4] = v;
        ((int4*)slab)[j4]   = Lv;
        float sv[4] = {v.x, v.y, v.z, v.w};
        int   lv[4] = {Lv.x, Lv.y, Lv.z, Lv.w};
#pragma unroll
        for (int c = 0; c < 4; c++) {
            float s = sv[c];
            if (lv[c] == li) { if (s < POSLIM) mn = fminf(mn, s); }
            else             { mx = fmaxf(mx, s); }
        }
    }
    __shared__ float smn[256], smx[256];
    smn[t] = mn; smx[t] = mx;
    __syncthreads();
    for (int o = 128; o > 0; o >>= 1) {
        if (t < o) { smn[t] = fminf(smn[t], smn[t + o]); smx[t] = fmaxf(smx[t], smx[t + o]); }
        __syncthreads();
    }
    const float tn = smn[0] - 0.1f;   // neg_sel: sim > tn
    const float tp = smx[0] + 0.1f;   // pos_sel: sim < tp

    // pass 2: masked exp-sums from SMEM
    float psum = 0.0f, nsum = 0.0f;
    int   pany = 0,    nany = 0;
    for (int j = t; j < BDIM; j += 256) {
        float s = srow[j];
        if (slab[j] == li) {
            if (s < POSLIM && s < tp) {
                pany = 1;
                psum += expf(-2.0f * (s - 0.5f));
            }
        } else {
            if (s > tn) {
                nany = 1;
                if (s >= 0.1f) nsum += expf(50.0f * (s - 0.5f));  // tail < 2e-9 dropped
            }
        }
    }
    __shared__ float sp[256], sn[256];
    __shared__ int   fp[256], fn[256];
    sp[t] = psum; sn[t] = nsum; fp[t] = pany; fn[t] = nany;
    __syncthreads();
    for (int o = 128; o > 0; o >>= 1) {
        if (t < o) {
            sp[t] += sp[t + o]; sn[t] += sn[t + o];
            fp[t] |= fp[t + o]; fn[t] |= fn[t + o];
        }
        __syncthreads();
    }
    if (t == 0) {
        bool valid = fp[0] && fn[0];
        float row_loss = 0.5f * log1pf(sp[0]) + 0.02f * log1pf(sn[0]);
        g_rowloss[i] = valid ? row_loss : 0.0f;
        g_validf[i]  = valid ? 1.0f : 0.0f;
    }
}

// ---------------- kernel 4: final reduction ----------------
__global__ void k_final(float* __restrict__ out, int out_size) {
    __shared__ float sl[256], sv[256];
    int t = threadIdx.x;
    float ls = 0.0f, vs = 0.0f;
    for (int i = t; i < BDIM; i += 256) { ls += g_rowloss[i]; vs += g_validf[i]; }
    sl[t] = ls; sv[t] = vs;
    __syncthreads();
    for (int o = 128; o > 0; o >>= 1) {
        if (t < o) { sl[t] += sl[t + o]; sv[t] += sv[t + o]; }
        __syncthreads();
    }
    if (t == 0) {
        if (out_size > 0) out[0] = sl[0] / (float)BDIM;
        if (out_size > 1) out[1] = 1.0f - sv[0] / (float)BDIM;
    }
}

// ---------------- launch ----------------
extern "C" void kernel_launch(void* const* d_in, const int* in_sizes, int n_in,
                              void* d_out, int out_size) {
    const float* feats  = (const float*)d_in[0];
    const int*   labels = (const int*)d_in[1];
    float* out = (float*)d_out;

    static bool attr_set = false;
    if (!attr_set) {
        cudaFuncSetAttribute(k_gemm, cudaFuncAttributeMaxDynamicSharedMemorySize, GEMM_SMEM);
        cudaFuncSetAttribute(k_row,  cudaFuncAttributeMaxDynamicSharedMemorySize, ROW_SMEM);
        attr_set = true;
    }

    k_load_labels<<<1, 1024>>>(labels);
    k_split<<<(BDIM * DDIM + 255) / 256, 256>>>(feats);
    k_gemm<<<NTILES, 256, GEMM_SMEM>>>();
    k_row<<<BDIM, 256, ROW_SMEM>>>();
    k_final<<<1, 256>>>(out, out_size);
}

// round 6
// speedup vs baseline: 2.7555x; 1.2498x over previous
#include <cuda_runtime.h>
#include <cuda_bf16.h>
#include <math.h>
#include <stdint.h>

#define BDIM 8192
#define DDIM 256
#define NBLK (BDIM / 128)
#define NTILES (NBLK * (NBLK + 1) / 2)   /* 2080 upper-triangular tiles */

// ---------------- device scratch (allocation-free workaround) ----------------
__device__ float         g_sim[(size_t)BDIM * BDIM];   // 256 MB
__device__ __nv_bfloat16 g_hi[BDIM * DDIM];            // bf16 high part
__device__ __nv_bfloat16 g_lo[BDIM * DDIM];            // bf16 residual
__device__ int           g_lab[BDIM];
__device__ unsigned      g_minpos_u[BDIM];             // ordered-uint encoded
__device__ unsigned      g_maxneg_u[BDIM];
__device__ float         g_rowloss[BDIM];
__device__ float         g_validf[BDIM];

// monotone float<->uint order mapping
__device__ __forceinline__ unsigned ordf(float f) {
    unsigned u = __float_as_uint(f);
    return (u & 0x80000000u) ? ~u : (u | 0x80000000u);
}
__device__ __forceinline__ float unordf(unsigned u) {
    unsigned b = (u & 0x80000000u) ? (u ^ 0x80000000u) : ~u;
    return __uint_as_float(b);
}
#define ORD_PINF 0xFF800000u
#define ORD_NINF 0x007FFFFFu

// ---------------- portable PTX helpers (sm_80+, pass plain sm_103 target) ---
__device__ __forceinline__ uint32_t smem_u32(const void* p) {
    uint32_t a;
    asm("{ .reg .u64 t; cvta.to.shared.u64 t, %1; cvt.u32.u64 %0, t; }" : "=r"(a) : "l"(p));
    return a;
}
#define CP_ASYNC16(dst, src) \
    asm volatile("cp.async.cg.shared.global [%0], [%1], 16;" :: "r"(dst), "l"(src) : "memory")
#define CP_COMMIT()  asm volatile("cp.async.commit_group;" ::: "memory")
#define CP_WAIT(n)   asm volatile("cp.async.wait_group %0;" :: "n"(n) : "memory")

__device__ __forceinline__ void ldm_x4(uint32_t* r, uint32_t addr) {
    asm volatile("ldmatrix.sync.aligned.m8n8.x4.shared.b16 {%0,%1,%2,%3}, [%4];"
                 : "=r"(r[0]), "=r"(r[1]), "=r"(r[2]), "=r"(r[3]) : "r"(addr));
}
__device__ __forceinline__ void mma_bf16(float* d, const uint32_t* a, const uint32_t* b) {
    asm volatile("mma.sync.aligned.m16n8k16.row.col.f32.bf16.bf16.f32 "
                 "{%0,%1,%2,%3}, {%4,%5,%6,%7}, {%8,%9}, {%0,%1,%2,%3};"
                 : "+f"(d[0]), "+f"(d[1]), "+f"(d[2]), "+f"(d[3])
                 : "r"(a[0]), "r"(a[1]), "r"(a[2]), "r"(a[3]), "r"(b[0]), "r"(b[1]));
}

// ---------------- kernel 0: labels (dtype-sniffing) + stat init -------------
__global__ void k_load_labels(const int* __restrict__ labels_raw) {
    __shared__ int s_nonzero_odd;
    const int t = threadIdx.x;
    if (t == 0) s_nonzero_odd = 0;
    __syncthreads();
    int local_or = 0;
    for (int i = t; i < BDIM / 2; i += blockDim.x)
        local_or |= labels_raw[2 * i + 1];
    if (local_or) atomicOr(&s_nonzero_odd, 1);
    __syncthreads();
    const bool is64 = (s_nonzero_odd == 0);
    for (int i = t; i < BDIM; i += blockDim.x) {
        g_lab[i] = is64 ? labels_raw[2 * i] : labels_raw[i];
        g_minpos_u[i] = ORD_PINF;
        g_maxneg_u[i] = ORD_NINF;
    }
}

// ---------------- kernel 1: bf16 split ----------------
__global__ void k_split(const float* __restrict__ feats) {
    int i = blockIdx.x * blockDim.x + threadIdx.x;
    if (i < BDIM * DDIM) {
        float a = feats[i];
        __nv_bfloat16 h = __float2bfloat16(a);
        g_hi[i] = h;
        g_lo[i] = __float2bfloat16(a - __bfloat162float(h));
    }
}

// ---------------- kernel 2: symmetric bf16 mma.sync GEMM + fused stats ------
// 128x128 CTA tile, 8 warps (4 row x 2 col), warp tile 32x64.
// 12 K-chunks: 3 products (hi*hi, hi*lo, lo*hi) x 4 chunks of K=64.
// Epilogue computes per-row AND per-col (mirror) masked min/max stats.
#define PITCH   72
#define CHUNKB  (128 * 144)           /* 18432 B per (tile,side) chunk */
#define GEMM_SMEM (3 * 2 * CHUNKB)    /* 110592 B */

__global__ __launch_bounds__(256, 2)
void k_gemm() {
    extern __shared__ char dsm[];
    __shared__ unsigned s_rmin[128], s_rmax[128], s_cmin[128], s_cmax[128];
    const uint32_t sbase = smem_u32(dsm);

    const int t    = threadIdx.x;
    const int lane = t & 31;
    const int wid  = t >> 5;
    const int wrow = wid & 3;          // 0..3
    const int wcol = wid >> 2;         // 0..1

    // decode upper-triangular tile index
    int L = blockIdx.x;
    int bi = (int)((129.0 - sqrt((double)(129 * 129 - 8 * L))) * 0.5);
    while (bi * (129 - bi) / 2 > L) bi--;
    while ((bi + 1) * (129 - (bi + 1)) / 2 <= L) bi++;
    const int bj = bi + (L - bi * (129 - bi) / 2);
    const int rowBase = bi * 128;
    const int colBase = bj * 128;
    const bool offdiag = (bi != bj);

    // init shared stats (synced by first mainloop __syncthreads)
    if (t < 128) {
        s_rmin[t] = ORD_PINF; s_rmax[t] = ORD_NINF;
        s_cmin[t] = ORD_PINF; s_cmax[t] = ORD_NINF;
    }

    float acc[2][8][4];
#pragma unroll
    for (int mt = 0; mt < 2; mt++)
#pragma unroll
        for (int nt = 0; nt < 8; nt++)
#pragma unroll
            for (int e = 0; e < 4; e++) acc[mt][nt][e] = 0.0f;

    auto load_chunk = [&](int idx, int stage) {
        const int p  = idx >> 2;
        const int kc = idx & 3;
        const __nv_bfloat16* rs = (p == 2) ? g_lo : g_hi;
        const __nv_bfloat16* cs = (p == 1) ? g_lo : g_hi;
        const uint32_t rdst = sbase + (stage * 2 + 0) * CHUNKB;
        const uint32_t cdst = sbase + (stage * 2 + 1) * CHUNKB;
        const char* rsrc = (const char*)rs + (size_t)rowBase * 512 + kc * 128;
        const char* csrc = (const char*)cs + (size_t)colBase * 512 + kc * 128;
#pragma unroll
        for (int i = 0; i < 4; i++) {
            int id = t + i * 256;            // 0..1023
            int r  = id >> 3;                // row 0..127
            int c  = (id & 7) * 16;          // byte col 0..112
            CP_ASYNC16(rdst + r * 144 + c, rsrc + (size_t)r * 512 + c);
            CP_ASYNC16(cdst + r * 144 + c, csrc + (size_t)r * 512 + c);
        }
    };

    load_chunk(0, 0); CP_COMMIT();
    load_chunk(1, 1); CP_COMMIT();

    const int lr = lane & 15;
    const int lc = (lane >> 4) * 16;

    for (int idx = 0; idx < 12; idx++) {
        if (idx + 2 < 12) {
            load_chunk(idx + 2, (idx + 2) % 3);
            CP_COMMIT();
            CP_WAIT(2);
        } else {
            CP_WAIT(0);
        }
        __syncthreads();

        const int stage = idx % 3;
        const uint32_t rb = sbase + (stage * 2 + 0) * CHUNKB;
        const uint32_t cb = sbase + (stage * 2 + 1) * CHUNKB;

#pragma unroll
        for (int kk = 0; kk < 4; kk++) {
            uint32_t a[2][4];
#pragma unroll
            for (int mt = 0; mt < 2; mt++)
                ldm_x4(a[mt], rb + (wrow * 32 + mt * 16 + lr) * 144 + kk * 32 + lc);
            uint32_t b[8][2];
#pragma unroll
            for (int n2 = 0; n2 < 4; n2++) {
                uint32_t q[4];
                ldm_x4(q, cb + (wcol * 64 + n2 * 16 + lr) * 144 + kk * 32 + lc);
                b[n2 * 2 + 0][0] = q[0]; b[n2 * 2 + 0][1] = q[2];
                b[n2 * 2 + 1][0] = q[1]; b[n2 * 2 + 1][1] = q[3];
            }
#pragma unroll
            for (int mt = 0; mt < 2; mt++)
#pragma unroll
                for (int nt = 0; nt < 8; nt++)
                    mma_bf16(acc[mt][nt], a[mt], b[nt]);
        }
        __syncthreads();
    }

    // ---- epilogue ----
    const float POSLIM = 1.0f - 1e-5f;
    const float PINF = __uint_as_float(0x7f800000u);
    const float NINF = __uint_as_float(0xff800000u);
    const int rq = lane >> 2;            // 0..7 row within 8-row group
    const int cq = (lane & 3) * 2;       // 0,2,4,6 col pair

    // direct store + row stats
#pragma unroll
    for (int mt = 0; mt < 2; mt++) {
#pragma unroll
        for (int h = 0; h < 2; h++) {
            const int rloc = wrow * 32 + mt * 16 + h * 8 + rq;
            const int row  = rowBase + rloc;
            const int lrow = g_lab[row];
            float* dst = &g_sim[(size_t)row * BDIM + colBase + wcol * 64 + cq];
            float mn = PINF, mx = NINF;
#pragma unroll
            for (int nt = 0; nt < 8; nt++) {
                float2 v = make_float2(acc[mt][nt][h * 2 + 0], acc[mt][nt][h * 2 + 1]);
                *(float2*)(dst + nt * 8) = v;
#pragma unroll
                for (int e = 0; e < 2; e++) {
                    float s = acc[mt][nt][h * 2 + e];
                    int lcb = g_lab[colBase + wcol * 64 + nt * 8 + cq + e];
                    if (lrow == lcb) { if (s < POSLIM) mn = fminf(mn, s); }
                    else             { mx = fmaxf(mx, s); }
                }
            }
            mn = fminf(mn, __shfl_xor_sync(~0u, mn, 1));
            mn = fminf(mn, __shfl_xor_sync(~0u, mn, 2));
            mx = fmaxf(mx, __shfl_xor_sync(~0u, mx, 1));
            mx = fmaxf(mx, __shfl_xor_sync(~0u, mx, 2));
            if ((lane & 3) == 0) {
                atomicMin(&s_rmin[rloc], ordf(mn));
                atomicMax(&s_rmax[rloc], ordf(mx));
            }
        }
    }

    if (offdiag) {
        // transposed mirror store + col stats
#pragma unroll
        for (int nt = 0; nt < 8; nt++) {
#pragma unroll
            for (int e = 0; e < 2; e++) {
                const int cloc = wcol * 64 + nt * 8 + cq + e;
                const int col  = colBase + cloc;
                const int lcb  = g_lab[col];
                float* dst = &g_sim[(size_t)col * BDIM + rowBase + wrow * 32];
                float mn = PINF, mx = NINF;
#pragma unroll
                for (int mt = 0; mt < 2; mt++) {
#pragma unroll
                    for (int h = 0; h < 2; h++) {
                        float s = acc[mt][nt][h * 2 + e];
                        dst[mt * 16 + h * 8 + rq] = s;
                        int lrow = g_lab[rowBase + wrow * 32 + mt * 16 + h * 8 + rq];
                        if (lrow == lcb) { if (s < POSLIM) mn = fminf(mn, s); }
                        else             { mx = fmaxf(mx, s); }
                    }
                }
                mn = fminf(mn, __shfl_xor_sync(~0u, mn, 4));
                mn = fminf(mn, __shfl_xor_sync(~0u, mn, 8));
                mn = fminf(mn, __shfl_xor_sync(~0u, mn, 16));
                mx = fmaxf(mx, __shfl_xor_sync(~0u, mx, 4));
                mx = fmaxf(mx, __shfl_xor_sync(~0u, mx, 8));
                mx = fmaxf(mx, __shfl_xor_sync(~0u, mx, 16));
                if (rq == 0) {
                    atomicMin(&s_cmin[cloc], ordf(mn));
                    atomicMax(&s_cmax[cloc], ordf(mx));
                }
            }
        }
    }

    __syncthreads();
    if (t < 128) {
        unsigned v;
        v = s_rmin[t]; if (v != ORD_PINF) atomicMin(&g_minpos_u[rowBase + t], v);
        v = s_rmax[t]; if (v != ORD_NINF) atomicMax(&g_maxneg_u[rowBase + t], v);
        if (offdiag) {
            v = s_cmin[t]; if (v != ORD_PINF) atomicMin(&g_minpos_u[colBase + t], v);
            v = s_cmax[t]; if (v != ORD_NINF) atomicMax(&g_maxneg_u[colBase + t], v);
        }
    }
}

// ---------------- kernel 3: single-pass masked exp-sums ---------------------
__global__ __launch_bounds__(256)
void k_row() {
    const int i = blockIdx.x;
    const int t = threadIdx.x;
    const int li = g_lab[i];
    const float tn = unordf(g_minpos_u[i]) - 0.1f;   // neg_sel: sim > tn
    const float tp = unordf(g_maxneg_u[i]) + 0.1f;   // pos_sel: sim < tp
    const float POSLIM = 1.0f - 1e-5f;

    float psum = 0.0f, nsum = 0.0f;
    int   pany = 0,    nany = 0;
    const float4* simrow = (const float4*)&g_sim[(size_t)i * BDIM];
    const int4*   lab4   = (const int4*)g_lab;

    for (int j4 = t; j4 < BDIM / 4; j4 += 256) {
        float4 v  = simrow[j4];
        int4   Lv = lab4[j4];
        float sv[4] = {v.x, v.y, v.z, v.w};
        int   lv[4] = {Lv.x, Lv.y, Lv.z, Lv.w};
#pragma unroll
        for (int c = 0; c < 4; c++) {
            float s = sv[c];
            if (lv[c] == li) {
                if (s < POSLIM && s < tp) {
                    pany = 1;
                    psum += expf(-2.0f * (s - 0.5f));
                }
            } else {
                if (s > tn) {
                    nany = 1;
                    if (s >= 0.1f) nsum += expf(50.0f * (s - 0.5f));  // tail < 2e-9 dropped
                }
            }
        }
    }
    __shared__ float sp[256], sn[256];
    __shared__ int   fp[256], fn[256];
    sp[t] = psum; sn[t] = nsum; fp[t] = pany; fn[t] = nany;
    __syncthreads();
    for (int o = 128; o > 0; o >>= 1) {
        if (t < o) {
            sp[t] += sp[t + o]; sn[t] += sn[t + o];
            fp[t] |= fp[t + o]; fn[t] |= fn[t + o];
        }
        __syncthreads();
    }
    if (t == 0) {
        bool valid = fp[0] && fn[0];
        float row_loss = 0.5f * log1pf(sp[0]) + 0.02f * log1pf(sn[0]);
        g_rowloss[i] = valid ? row_loss : 0.0f;
        g_validf[i]  = valid ? 1.0f : 0.0f;
    }
}

// ---------------- kernel 4: final reduction ----------------
__global__ void k_final(float* __restrict__ out, int out_size) {
    __shared__ float sl[256], sv[256];
    int t = threadIdx.x;
    float ls = 0.0f, vs = 0.0f;
    for (int i = t; i < BDIM; i += 256) { ls += g_rowloss[i]; vs += g_validf[i]; }
    sl[t] = ls; sv[t] = vs;
    __syncthreads();
    for (int o = 128; o > 0; o >>= 1) {
        if (t < o) { sl[t] += sl[t + o]; sv[t] += sv[t + o]; }
        __syncthreads();
    }
    if (t == 0) {
        if (out_size > 0) out[0] = sl[0] / (float)BDIM;
        if (out_size > 1) out[1] = 1.0f - sv[0] / (float)BDIM;
    }
}

// ---------------- launch ----------------
extern "C" void kernel_launch(void* const* d_in, const int* in_sizes, int n_in,
                              void* d_out, int out_size) {
    const float* feats  = (const float*)d_in[0];
    const int*   labels = (const int*)d_in[1];
    float* out = (float*)d_out;

    cudaFuncSetAttribute(k_gemm, cudaFuncAttributeMaxDynamicSharedMemorySize, GEMM_SMEM);

    k_load_labels<<<1, 1024>>>(labels);
    k_split<<<(BDIM * DDIM + 255) / 256, 256>>>(feats);
    k_gemm<<<NTILES, 256, GEMM_SMEM>>>();
    k_row<<<BDIM, 256>>>();
    k_final<<<1, 256>>>(out, out_size);
}

// round 8
// speedup vs baseline: 3.1088x; 1.1282x over previous
#include <cuda_runtime.h>
#include <cuda_fp16.h>
#include <math.h>
#include <stdint.h>

#define BDIM 8192
#define DDIM 256
#define NBLK (BDIM / 128)
#define NTILES (NBLK * (NBLK + 1) / 2)   /* 2080 upper-triangular tiles */

// ---------------- device scratch (allocation-free workaround) ----------------
__device__ float    g_sim[(size_t)BDIM * BDIM];   // 256 MB
__device__ __half   g_hi[BDIM * DDIM];            // fp16 hi = fp16(a)
__device__ __half   g_q [BDIM * DDIM];            // fp16 q  = fp16(2a - hi)
__device__ int      g_lab[BDIM];
__device__ unsigned g_minpos_u[BDIM];             // ordered-uint encoded
__device__ unsigned g_maxneg_u[BDIM];
__device__ float    g_rowloss[BDIM];
__device__ float    g_validf[BDIM];

// monotone float<->uint order mapping
__device__ __forceinline__ unsigned ordf(float f) {
    unsigned u = __float_as_uint(f);
    return (u & 0x80000000u) ? ~u : (u | 0x80000000u);
}
__device__ __forceinline__ float unordf(unsigned u) {
    unsigned b = (u & 0x80000000u) ? (u ^ 0x80000000u) : ~u;
    return __uint_as_float(b);
}
#define ORD_PINF 0xFF800000u
#define ORD_NINF 0x007FFFFFu

// ---------------- portable PTX helpers (sm_80+, pass plain sm_103 target) ---
__device__ __forceinline__ uint32_t smem_u32(const void* p) {
    uint32_t a;
    asm("{ .reg .u64 t; cvta.to.shared.u64 t, %1; cvt.u32.u64 %0, t; }" : "=r"(a) : "l"(p));
    return a;
}
#define CP_ASYNC16(dst, src) \
    asm volatile("cp.async.cg.shared.global [%0], [%1], 16;" :: "r"(dst), "l"(src) : "memory")
#define CP_COMMIT()  asm volatile("cp.async.commit_group;" ::: "memory")
#define CP_WAIT(n)   asm volatile("cp.async.wait_group %0;" :: "n"(n) : "memory")

__device__ __forceinline__ void ldm_x4(uint32_t* r, uint32_t addr) {
    asm volatile("ldmatrix.sync.aligned.m8n8.x4.shared.b16 {%0,%1,%2,%3}, [%4];"
                 : "=r"(r[0]), "=r"(r[1]), "=r"(r[2]), "=r"(r[3]) : "r"(addr));
}
__device__ __forceinline__ void mma_f16(float* d, const uint32_t* a, const uint32_t* b) {
    asm volatile("mma.sync.aligned.m16n8k16.row.col.f32.f16.f16.f32 "
                 "{%0,%1,%2,%3}, {%4,%5,%6,%7}, {%8,%9}, {%0,%1,%2,%3};"
                 : "+f"(d[0]), "+f"(d[1]), "+f"(d[2]), "+f"(d[3])
                 : "r"(a[0]), "r"(a[1]), "r"(a[2]), "r"(a[3]), "r"(b[0]), "r"(b[1]));
}

// ---------------- kernel 0: labels (dtype-sniffing) + stat init -------------
__global__ void k_load_labels(const int* __restrict__ labels_raw) {
    __shared__ int s_nonzero_odd;
    const int t = threadIdx.x;
    if (t == 0) s_nonzero_odd = 0;
    __syncthreads();
    int local_or = 0;
    for (int i = t; i < BDIM / 2; i += blockDim.x)
        local_or |= labels_raw[2 * i + 1];
    if (local_or) atomicOr(&s_nonzero_odd, 1);
    __syncthreads();
    const bool is64 = (s_nonzero_odd == 0);
    for (int i = t; i < BDIM; i += blockDim.x) {
        g_lab[i] = is64 ? labels_raw[2 * i] : labels_raw[i];
        g_minpos_u[i] = ORD_PINF;
        g_maxneg_u[i] = ORD_NINF;
    }
}

// ---------------- kernel 1: fp16 hi/q split ----------------
// hi = fp16(a); q = fp16(2a - hi). Then 0.5*(hi_i q_j + q_i hi_j) = a_i a_j - lo_i lo_j.
__global__ void k_split(const float* __restrict__ feats) {
    int i = blockIdx.x * blockDim.x + threadIdx.x;
    if (i < BDIM * DDIM) {
        float a = feats[i];
        __half h = __float2half(a);
        g_hi[i] = h;
        g_q[i]  = __float2half(2.0f * a - __half2float(h));
    }
}

// ---------------- kernel 2: symmetric fp16 mma.sync GEMM + fused stats ------
// 128x128 CTA tile, 8 warps (4 row x 2 col), warp tile 32x64.
// Per K=32 sub-chunk stage 4 operand sub-tiles (hi_r, q_r, hi_c, q_c);
// run 2 products (hi_r x q_c, q_r x hi_c) into ONE accumulator; x0.5 at end.
// Pitch 80B: 16B-aligned AND conflict-free (20r mod 32 covers all banks).
// 2-stage cp.async pipeline (81920 B smem -> 2 CTA/SM).
#define SUBT   (128 * 80)             /* 10240 B: 128 rows x 32 fp16, pitch 80 */
#define STAGEB (4 * SUBT)             /* 40960 B per stage */
#define GEMM_SMEM (2 * STAGEB)        /* 81920 B */

__global__ __launch_bounds__(256, 2)
void k_gemm() {
    extern __shared__ char dsm[];
    __shared__ unsigned s_rmin[128], s_rmax[128], s_cmin[128], s_cmax[128];
    const uint32_t sbase = smem_u32(dsm);

    const int t    = threadIdx.x;
    const int lane = t & 31;
    const int wid  = t >> 5;
    const int wrow = wid & 3;          // 0..3
    const int wcol = wid >> 2;         // 0..1

    // decode upper-triangular tile index
    int L = blockIdx.x;
    int bi = (int)((129.0 - sqrt((double)(129 * 129 - 8 * L))) * 0.5);
    while (bi * (129 - bi) / 2 > L) bi--;
    while ((bi + 1) * (129 - (bi + 1)) / 2 <= L) bi++;
    const int bj = bi + (L - bi * (129 - bi) / 2);
    const int rowBase = bi * 128;
    const int colBase = bj * 128;
    const bool offdiag = (bi != bj);

    if (t < 128) {
        s_rmin[t] = ORD_PINF; s_rmax[t] = ORD_NINF;
        s_cmin[t] = ORD_PINF; s_cmax[t] = ORD_NINF;
    }

    float acc[2][8][4];
#pragma unroll
    for (int mt = 0; mt < 2; mt++)
#pragma unroll
        for (int nt = 0; nt < 8; nt++)
#pragma unroll
            for (int e = 0; e < 4; e++) acc[mt][nt][e] = 0.0f;

    // stage loader: ks = K sub-chunk (0..7, 32 fp16 = 64 B per row)
    auto load_stage = [&](int ks, int stage) {
        const uint32_t sb = sbase + stage * STAGEB;
        const char* srcs[4] = {
            (const char*)g_hi + (size_t)rowBase * 512,
            (const char*)g_q  + (size_t)rowBase * 512,
            (const char*)g_hi + (size_t)colBase * 512,
            (const char*)g_q  + (size_t)colBase * 512 };
        const int nsub = offdiag ? 8 : 4;   // diag: only row-side sub-tiles
#pragma unroll
        for (int i = 0; i < 8; i++) {
            if (i >= nsub) break;
            int id  = t + i * 256;           // 0..2047
            int sub = id >> 9;               // 0..3
            int r   = (id >> 2) & 127;       // row
            int c   = (id & 3) * 16;         // byte col 0..48
            CP_ASYNC16(sb + sub * SUBT + r * 80 + c,
                       srcs[sub] + (size_t)r * 512 + ks * 64 + c);
        }
    };

    load_stage(0, 0); CP_COMMIT();

    const int lr = lane & 15;
    const int lc = (lane >> 4) * 16;

    for (int ks = 0; ks < 8; ks++) {
        if (ks + 1 < 8) {
            load_stage(ks + 1, (ks + 1) & 1);
            CP_COMMIT();
            CP_WAIT(1);
        } else {
            CP_WAIT(0);
        }
        __syncthreads();

        const uint32_t sb = sbase + (ks & 1) * STAGEB;
        const uint32_t hr = sb;
        const uint32_t qr = sb + SUBT;
        const uint32_t hc = offdiag ? sb + 2 * SUBT : hr;
        const uint32_t qc = offdiag ? sb + 3 * SUBT : qr;

#pragma unroll
        for (int kk = 0; kk < 2; kk++) {
#pragma unroll
            for (int p = 0; p < 2; p++) {
                const uint32_t ab = (p == 0) ? hr : qr;
                const uint32_t bb = (p == 0) ? qc : hc;
                uint32_t a[2][4];
#pragma unroll
                for (int mt = 0; mt < 2; mt++)
                    ldm_x4(a[mt], ab + (wrow * 32 + mt * 16 + lr) * 80 + kk * 32 + lc);
                uint32_t b[8][2];
#pragma unroll
                for (int n2 = 0; n2 < 4; n2++) {
                    uint32_t qv[4];
                    ldm_x4(qv, bb + (wcol * 64 + n2 * 16 + lr) * 80 + kk * 32 + lc);
                    b[n2 * 2 + 0][0] = qv[0]; b[n2 * 2 + 0][1] = qv[2];
                    b[n2 * 2 + 1][0] = qv[1]; b[n2 * 2 + 1][1] = qv[3];
                }
#pragma unroll
                for (int mt = 0; mt < 2; mt++)
#pragma unroll
                    for (int nt = 0; nt < 8; nt++)
                        mma_f16(acc[mt][nt], a[mt], b[nt]);
            }
        }
        __syncthreads();
    }

    // ---- scale: sim = 0.5 * (P1 + P2) ----
#pragma unroll
    for (int mt = 0; mt < 2; mt++)
#pragma unroll
        for (int nt = 0; nt < 8; nt++)
#pragma unroll
            for (int e = 0; e < 4; e++) acc[mt][nt][e] *= 0.5f;

    // ---- epilogue: stores + fused row/col stats ----
    const float POSLIM = 1.0f - 1e-5f;
    const float PINF = __uint_as_float(0x7f800000u);
    const float NINF = __uint_as_float(0xff800000u);
    const int rq = lane >> 2;            // 0..7 row within 8-row group
    const int cq = (lane & 3) * 2;       // 0,2,4,6 col pair

    // direct store + row stats
#pragma unroll
    for (int mt = 0; mt < 2; mt++) {
#pragma unroll
        for (int h = 0; h < 2; h++) {
            const int rloc = wrow * 32 + mt * 16 + h * 8 + rq;
            const int row  = rowBase + rloc;
            const int lrow = g_lab[row];
            float* dst = &g_sim[(size_t)row * BDIM + colBase + wcol * 64 + cq];
            float mn = PINF, mx = NINF;
#pragma unroll
            for (int nt = 0; nt < 8; nt++) {
                float2 v = make_float2(acc[mt][nt][h * 2 + 0], acc[mt][nt][h * 2 + 1]);
                *(float2*)(dst + nt * 8) = v;
#pragma unroll
                for (int e = 0; e < 2; e++) {
                    float s = acc[mt][nt][h * 2 + e];
                    int lcb = g_lab[colBase + wcol * 64 + nt * 8 + cq + e];
                    if (lrow == lcb) { if (s < POSLIM) mn = fminf(mn, s); }
                    else             { mx = fmaxf(mx, s); }
                }
            }
            mn = fminf(mn, __shfl_xor_sync(~0u, mn, 1));
            mn = fminf(mn, __shfl_xor_sync(~0u, mn, 2));
            mx = fmaxf(mx, __shfl_xor_sync(~0u, mx, 1));
            mx = fmaxf(mx, __shfl_xor_sync(~0u, mx, 2));
            if ((lane & 3) == 0) {
                atomicMin(&s_rmin[rloc], ordf(mn));
                atomicMax(&s_rmax[rloc], ordf(mx));
            }
        }
    }

    if (offdiag) {
        // transposed mirror store + col stats
#pragma unroll
        for (int nt = 0; nt < 8; nt++) {
#pragma unroll
            for (int e = 0; e < 2; e++) {
                const int cloc = wcol * 64 + nt * 8 + cq + e;
                const int col  = colBase + cloc;
                const int lcb  = g_lab[col];
                float* dst = &g_sim[(size_t)col * BDIM + rowBase + wrow * 32];
                float mn = PINF, mx = NINF;
#pragma unroll
                for (int mt = 0; mt < 2; mt++) {
#pragma unroll
                    for (int h = 0; h < 2; h++) {
                        float s = acc[mt][nt][h * 2 + e];
                        dst[mt * 16 + h * 8 + rq] = s;
                        int lrow = g_lab[rowBase + wrow * 32 + mt * 16 + h * 8 + rq];
                        if (lrow == lcb) { if (s < POSLIM) mn = fminf(mn, s); }
                        else             { mx = fmaxf(mx, s); }
                    }
                }
                mn = fminf(mn, __shfl_xor_sync(~0u, mn, 4));
                mn = fminf(mn, __shfl_xor_sync(~0u, mn, 8));
                mn = fminf(mn, __shfl_xor_sync(~0u, mn, 16));
                mx = fmaxf(mx, __shfl_xor_sync(~0u, mx, 4));
                mx = fmaxf(mx, __shfl_xor_sync(~0u, mx, 8));
                mx = fmaxf(mx, __shfl_xor_sync(~0u, mx, 16));
                if (rq == 0) {
                    atomicMin(&s_cmin[cloc], ordf(mn));
                    atomicMax(&s_cmax[cloc], ordf(mx));
                }
            }
        }
    }

    __syncthreads();
    if (t < 128) {
        unsigned v;
        v = s_rmin[t]; if (v != ORD_PINF) atomicMin(&g_minpos_u[rowBase + t], v);
        v = s_rmax[t]; if (v != ORD_NINF) atomicMax(&g_maxneg_u[rowBase + t], v);
        if (offdiag) {
            v = s_cmin[t]; if (v != ORD_PINF) atomicMin(&g_minpos_u[colBase + t], v);
            v = s_cmax[t]; if (v != ORD_NINF) atomicMax(&g_maxneg_u[colBase + t], v);
        }
    }
}

// ---------------- kernel 3: single-pass masked exp-sums ---------------------
__global__ __launch_bounds__(256)
void k_row() {
    const int i = blockIdx.x;
    const int t = threadIdx.x;
    const int li = g_lab[i];
    const float tn = unordf(g_minpos_u[i]) - 0.1f;   // neg_sel: sim > tn
    const float tp = unordf(g_maxneg_u[i]) + 0.1f;   // pos_sel: sim < tp
    const float POSLIM = 1.0f - 1e-5f;

    float psum = 0.0f, nsum = 0.0f;
    int   pany = 0,    nany = 0;
    const float4* simrow = (const float4*)&g_sim[(size_t)i * BDIM];
    const int4*   lab4   = (const int4*)g_lab;

    for (int j4 = t; j4 < BDIM / 4; j4 += 256) {
        float4 v  = simrow[j4];
        int4   Lv = lab4[j4];
        float sv[4] = {v.x, v.y, v.z, v.w};
        int   lv[4] = {Lv.x, Lv.y, Lv.z, Lv.w};
#pragma unroll
        for (int c = 0; c < 4; c++) {
            float s = sv[c];
            if (lv[c] == li) {
                if (s < POSLIM && s < tp) {
                    pany = 1;
                    psum += expf(-2.0f * (s - 0.5f));
                }
            } else {
                if (s > tn) {
                    nany = 1;
                    if (s >= 0.1f) nsum += expf(50.0f * (s - 0.5f));  // tail < 2e-9 dropped
                }
            }
        }
    }
    __shared__ float sp[256], sn[256];
    __shared__ int   fp[256], fn[256];
    sp[t] = psum; sn[t] = nsum; fp[t] = pany; fn[t] = nany;
    __syncthreads();
    for (int o = 128; o > 0; o >>= 1) {
        if (t < o) {
            sp[t] += sp[t + o]; sn[t] += sn[t + o];
            fp[t] |= fp[t + o]; fn[t] |= fn[t + o];
        }
        __syncthreads();
    }
    if (t == 0) {
        bool valid = fp[0] && fn[0];
        float row_loss = 0.5f * log1pf(sp[0]) + 0.02f * log1pf(sn[0]);
        g_rowloss[i] = valid ? row_loss : 0.0f;
        g_validf[i]  = valid ? 1.0f : 0.0f;
    }
}

// ---------------- kernel 4: final reduction ----------------
__global__ void k_final(float* __restrict__ out, int out_size) {
    __shared__ float sl[256], sv[256];
    int t = threadIdx.x;
    float ls = 0.0f, vs = 0.0f;
    for (int i = t; i < BDIM; i += 256) { ls += g_rowloss[i]; vs += g_validf[i]; }
    sl[t] = ls; sv[t] = vs;
    __syncthreads();
    for (int o = 128; o > 0; o >>= 1) {
        if (t < o) { sl[t] += sl[t + o]; sv[t] += sv[t + o]; }
        __syncthreads();
    }
    if (t == 0) {
        if (out_size > 0) out[0] = sl[0] / (float)BDIM;
        if (out_size > 1) out[1] = 1.0f - sv[0] / (float)BDIM;
    }
}

// ---------------- launch ----------------
extern "C" void kernel_launch(void* const* d_in, const int* in_sizes, int n_in,
                              void* d_out, int out_size) {
    const float* feats  = (const float*)d_in[0];
    const int*   labels = (const int*)d_in[1];
    float* out = (float*)d_out;

    cudaFuncSetAttribute(k_gemm, cudaFuncAttributeMaxDynamicSharedMemorySize, GEMM_SMEM);

    k_load_labels<<<1, 1024>>>(labels);
    k_split<<<(BDIM * DDIM + 255) / 256, 256>>>(feats);
    k_gemm<<<NTILES, 256, GEMM_SMEM>>>();
    k_row<<<BDIM, 256>>>();
    k_final<<<1, 256>>>(out, out_size);
}